// round 7
// baseline (speedup 1.0000x reference)
#include <cuda_runtime.h>
#include <cuda_bf16.h>
#include <cuda_fp16.h>
#include <math.h>
#include <stdint.h>

#define N_NODES 50000
#define N_EDGES 800000
#define IN_DIM  512
#define HIDDEN  128
#define OUT_DIM 64
#define EPS_F   0.3f
#define SCAN_NB 49           // ceil(50000/1024)

// ---------------- scratch (device globals; no allocation allowed) -----------
__device__ __half g_h0h[N_NODES * HIDDEN];   // raw fp16 (gathers + residual)
__device__ __half g_hAh[N_NODES * HIDDEN];   // layer-0 out fp16
__device__ float  g_hB [N_NODES * HIDDEN];   // layer-1 out fp32 (head input)
__device__ float  g_sdst0[N_NODES];          // layer-0 dst gate scalar
__device__ float  g_ssrc0[N_NODES];          // layer-0 src gate scalar
__device__ float  g_sdst1[N_NODES];          // layer-1 dst gate scalar
__device__ float2 g_nsd0[N_NODES];           // layer-0 {ssrc[n], d[n]}
__device__ float2 g_nsd1[N_NODES];           // layer-1 {ssrc[n], d[n]}
__device__ int    g_counts[N_NODES];
__device__ int    g_rowptr[N_NODES + 1];
__device__ int    g_cursor[N_NODES];
__device__ int    g_psrc[N_EDGES];           // src per CSR position
__device__ int    g_blocksums[64];
__device__ __nv_bfloat16 g_w_hi[HIDDEN * IN_DIM];
__device__ __nv_bfloat16 g_w_lo[HIDDEN * IN_DIM];

// ---------------- W split conversion + zero accumulators ---------------------
__global__ void wconv_kernel(const float* __restrict__ W) {
    int i = blockIdx.x * blockDim.x + threadIdx.x;
    if (i < HIDDEN * IN_DIM) {
        float v = W[i];
        __nv_bfloat16 h = __float2bfloat16_rn(v);
        g_w_hi[i] = h;
        g_w_lo[i] = __float2bfloat16_rn(v - __bfloat162float(h));
    }
    if (i < N_NODES) {
        g_counts[i] = 0;
        g_sdst0[i] = 0.f;
        g_ssrc0[i] = 0.f;
    }
}

// ---------------- GEMM1 via split-bf16 tensor cores + fused gate proj --------
#define GP 20  // smem row pitch in 32-bit words

__device__ __forceinline__ uint32_t pack2(__nv_bfloat16 a, __nv_bfloat16 b) {
    uint16_t ua = *reinterpret_cast<uint16_t*>(&a);
    uint16_t ub = *reinterpret_cast<uint16_t*>(&b);
    return (uint32_t)ua | ((uint32_t)ub << 16);
}

__device__ __forceinline__ void mma_bf16(float* d, const uint32_t* a,
                                         uint32_t b0, uint32_t b1) {
    asm volatile(
        "mma.sync.aligned.m16n8k16.row.col.f32.bf16.bf16.f32 "
        "{%0,%1,%2,%3},{%4,%5,%6,%7},{%8,%9},{%0,%1,%2,%3};\n"
        : "+f"(d[0]), "+f"(d[1]), "+f"(d[2]), "+f"(d[3])
        : "r"(a[0]), "r"(a[1]), "r"(a[2]), "r"(a[3]), "r"(b0), "r"(b1));
}

__global__ void __launch_bounds__(256)
gemm1_mma_kernel(const float* __restrict__ A, const float* __restrict__ bias,
                 const float* __restrict__ gate_w) {
    __shared__ uint32_t asH[128 * GP], asL[128 * GP];
    __shared__ uint32_t bsH[128 * GP], bsL[128 * GP];
    const int tid = threadIdx.x;
    const int brow = blockIdx.x * 128;
    const int warp = tid >> 5, lane = tid & 31;
    const int wm = warp >> 1, wn = warp & 1;
    const int ldrow = tid >> 1, half = tid & 1;

    float acc[2][8][4];
#pragma unroll
    for (int mt = 0; mt < 2; mt++)
#pragma unroll
        for (int nt = 0; nt < 8; nt++)
#pragma unroll
            for (int q = 0; q < 4; q++) acc[mt][nt][q] = 0.f;

    const int arow = min(brow + ldrow, N_NODES - 1);
    const float4* __restrict__ ag =
        (const float4*)&A[(size_t)arow * IN_DIM + half * 16];
    const uint4* __restrict__ bgh =
        (const uint4*)&g_w_hi[ldrow * IN_DIM + half * 16];
    const uint4* __restrict__ bgl =
        (const uint4*)&g_w_lo[ldrow * IN_DIM + half * 16];

    for (int k0 = 0; k0 < IN_DIM; k0 += 32) {
#pragma unroll
        for (int q = 0; q < 4; q++) {
            float4 v = ag[(k0 >> 2) + q];
            __nv_bfloat16 hx = __float2bfloat16_rn(v.x);
            __nv_bfloat16 hy = __float2bfloat16_rn(v.y);
            __nv_bfloat16 hz = __float2bfloat16_rn(v.z);
            __nv_bfloat16 hw = __float2bfloat16_rn(v.w);
            __nv_bfloat16 lx = __float2bfloat16_rn(v.x - __bfloat162float(hx));
            __nv_bfloat16 ly = __float2bfloat16_rn(v.y - __bfloat162float(hy));
            __nv_bfloat16 lz = __float2bfloat16_rn(v.z - __bfloat162float(hz));
            __nv_bfloat16 lw = __float2bfloat16_rn(v.w - __bfloat162float(hw));
            int w = half * 8 + q * 2;
            *(uint2*)&asH[ldrow * GP + w] = make_uint2(pack2(hx, hy), pack2(hz, hw));
            *(uint2*)&asL[ldrow * GP + w] = make_uint2(pack2(lx, ly), pack2(lz, lw));
        }
#pragma unroll
        for (int q = 0; q < 2; q++) {
            uint4 bh = bgh[(k0 >> 3) + q];
            uint4 bl = bgl[(k0 >> 3) + q];
            *(uint4*)&bsH[ldrow * GP + half * 8 + q * 4] = bh;
            *(uint4*)&bsL[ldrow * GP + half * 8 + q * 4] = bl;
        }
        __syncthreads();
#pragma unroll
        for (int kk = 0; kk < 2; kk++) {
            const int kw = kk * 8 + (lane & 3);
            uint32_t aH[2][4], aL[2][4];
#pragma unroll
            for (int mt = 0; mt < 2; mt++) {
                int r = wm * 32 + mt * 16 + (lane >> 2);
                aH[mt][0] = asH[r * GP + kw];
                aH[mt][1] = asH[(r + 8) * GP + kw];
                aH[mt][2] = asH[r * GP + kw + 4];
                aH[mt][3] = asH[(r + 8) * GP + kw + 4];
                aL[mt][0] = asL[r * GP + kw];
                aL[mt][1] = asL[(r + 8) * GP + kw];
                aL[mt][2] = asL[r * GP + kw + 4];
                aL[mt][3] = asL[(r + 8) * GP + kw + 4];
            }
#pragma unroll
            for (int nt = 0; nt < 8; nt++) {
                int n = wn * 64 + nt * 8 + (lane >> 2);
                uint32_t bH0 = bsH[n * GP + kw], bH1 = bsH[n * GP + kw + 4];
                uint32_t bL0 = bsL[n * GP + kw], bL1 = bsL[n * GP + kw + 4];
#pragma unroll
                for (int mt = 0; mt < 2; mt++) {
                    mma_bf16(acc[mt][nt], aH[mt], bH0, bH1);
                    mma_bf16(acc[mt][nt], aL[mt], bH0, bH1);
                    mma_bf16(acc[mt][nt], aH[mt], bL0, bL1);
                }
            }
        }
        __syncthreads();
    }
    // epilogue: bias + relu + fp16 store + fused layer-0 gate partial dots
#pragma unroll
    for (int mt = 0; mt < 2; mt++) {
        int r0 = brow + wm * 32 + mt * 16 + (lane >> 2);
        float pd0 = 0.f, ps0 = 0.f, pd1 = 0.f, ps1 = 0.f;
#pragma unroll
        for (int nt = 0; nt < 8; nt++) {
            int c = wn * 64 + nt * 8 + (lane & 3) * 2;
            float b0 = __ldg(&bias[c]), b1 = __ldg(&bias[c + 1]);
            float wd0 = __ldg(&gate_w[c]), wd1 = __ldg(&gate_w[c + 1]);
            float ws0 = __ldg(&gate_w[HIDDEN + c]), ws1 = __ldg(&gate_w[HIDDEN + c + 1]);
            float v00 = fmaxf(acc[mt][nt][0] + b0, 0.f);
            float v01 = fmaxf(acc[mt][nt][1] + b1, 0.f);
            float v10 = fmaxf(acc[mt][nt][2] + b0, 0.f);
            float v11 = fmaxf(acc[mt][nt][3] + b1, 0.f);
            if (r0 < N_NODES)
                *(__half2*)&g_h0h[(size_t)r0 * HIDDEN + c] = __floats2half2_rn(v00, v01);
            if (r0 + 8 < N_NODES)
                *(__half2*)&g_h0h[(size_t)(r0 + 8) * HIDDEN + c] = __floats2half2_rn(v10, v11);
            pd0 = fmaf(v00, wd0, fmaf(v01, wd1, pd0));
            ps0 = fmaf(v00, ws0, fmaf(v01, ws1, ps0));
            pd1 = fmaf(v10, wd0, fmaf(v11, wd1, pd1));
            ps1 = fmaf(v10, ws0, fmaf(v11, ws1, ps1));
        }
        // reduce across the 4 col-group lanes (same quad)
#pragma unroll
        for (int off = 1; off < 4; off <<= 1) {
            pd0 += __shfl_xor_sync(0xffffffffu, pd0, off);
            ps0 += __shfl_xor_sync(0xffffffffu, ps0, off);
            pd1 += __shfl_xor_sync(0xffffffffu, pd1, off);
            ps1 += __shfl_xor_sync(0xffffffffu, ps1, off);
        }
        if ((lane & 3) == 0) {
            if (r0 < N_NODES) {
                atomicAdd(&g_sdst0[r0], pd0);
                atomicAdd(&g_ssrc0[r0], ps0);
            }
            if (r0 + 8 < N_NODES) {
                atomicAdd(&g_sdst0[r0 + 8], pd1);
                atomicAdd(&g_ssrc0[r0 + 8], ps1);
            }
        }
    }
}

// ---------------- CSR build -------------------------------------------------
__global__ void hist_kernel(const int* __restrict__ dst) {
    int i = blockIdx.x * blockDim.x + threadIdx.x;
    if (i < N_EDGES) atomicAdd(&g_counts[dst[i]], 1);
}
__global__ void scan_blocks_kernel() {
    __shared__ int wsum[32];
    const int t = threadIdx.x, lane = t & 31, wid = t >> 5;
    const int i = blockIdx.x * 1024 + t;
    int v = (i < N_NODES) ? g_counts[i] : 0;
    int x = v;
#pragma unroll
    for (int off = 1; off < 32; off <<= 1) {
        int y = __shfl_up_sync(0xffffffffu, x, off);
        if (lane >= off) x += y;
    }
    if (lane == 31) wsum[wid] = x;
    __syncthreads();
    if (wid == 0) {
        int s = wsum[lane];
#pragma unroll
        for (int off = 1; off < 32; off <<= 1) {
            int y = __shfl_up_sync(0xffffffffu, s, off);
            if (lane >= off) s += y;
        }
        wsum[lane] = s;
    }
    __syncthreads();
    int incl = x + (wid > 0 ? wsum[wid - 1] : 0);
    if (i < N_NODES) g_rowptr[i] = incl - v;
    if (t == 1023) g_blocksums[blockIdx.x] = incl;
}
__global__ void scan_sums_kernel() {
    __shared__ int sm[64];
    int t = threadIdx.x;
    int v = (t < SCAN_NB) ? g_blocksums[t] : 0;
    sm[t] = v;
    __syncthreads();
    for (int off = 1; off < 64; off <<= 1) {
        int x = (t >= off) ? sm[t - off] : 0;
        __syncthreads();
        sm[t] += x;
        __syncthreads();
    }
    if (t < SCAN_NB) g_blocksums[t] = sm[t] - v;
}
// add offsets + pack layer-0 node {ssrc, d}
__global__ void add_offsets_kernel(const float* __restrict__ d) {
    int i = blockIdx.x * blockDim.x + threadIdx.x;
    if (i < N_NODES) {
        int r = g_rowptr[i] + g_blocksums[i >> 10];
        g_rowptr[i] = r;
        g_cursor[i] = r;
        g_nsd0[i] = make_float2(g_ssrc0[i], d[i]);
    }
    if (i == 0) g_rowptr[N_NODES] = N_EDGES;
}
__global__ void scatter_kernel(const int* __restrict__ src,
                               const int* __restrict__ dst) {
    int i = blockIdx.x * blockDim.x + threadIdx.x;
    if (i < N_EDGES) {
        int pos = atomicAdd(&g_cursor[dst[i]], 1);
        g_psrc[pos] = src[i];
    }
}

// ---------------- aggregation (fused edge coefficients) ----------------------
__device__ __forceinline__ float4 h4_to_f4(uint2 q) {
    __half2 a = *reinterpret_cast<__half2*>(&q.x);
    __half2 b = *reinterpret_cast<__half2*>(&q.y);
    float2 fa = __half22float2(a), fb = __half22float2(b);
    return make_float4(fa.x, fa.y, fb.x, fb.y);
}

// LAYER 0: gather g_h0h -> g_hAh fp16, + fused layer-1 gate scalars
// LAYER 1: gather g_hAh -> g_hB fp32
template <int LAYER>
__global__ void agg_kernel(const float* __restrict__ dvec,
                           const float* __restrict__ gate_b,
                           const float* __restrict__ gate_w_next) {
    int warp = (blockIdx.x * blockDim.x + threadIdx.x) >> 5;
    int lane = threadIdx.x & 31;
    if (warp >= N_NODES) return;
    const __half*  __restrict__ h_in = (LAYER == 0) ? g_h0h : g_hAh;
    const float*   __restrict__ sdst = (LAYER == 0) ? g_sdst0 : g_sdst1;
    const float2*  __restrict__ nsd  = (LAYER == 0) ? g_nsd0  : g_nsd1;

    const float sd = __ldg(&sdst[warp]);
    const float dt = __ldg(&dvec[warp]);
    const float gb = __ldg(&gate_b[LAYER]);
    const float dtb = sd + gb;      // warp-uniform part of tanh argument

    int rs = g_rowptr[warp], re = g_rowptr[warp + 1];
    float4 acc = make_float4(0.f, 0.f, 0.f, 0.f);
    int p = rs;
    for (; p + 3 < re; p += 4) {
        int s0 = __ldg(&g_psrc[p]);
        int s1 = __ldg(&g_psrc[p + 1]);
        int s2 = __ldg(&g_psrc[p + 2]);
        int s3 = __ldg(&g_psrc[p + 3]);
        float2 n0 = __ldg(&nsd[s0]);
        float2 n1 = __ldg(&nsd[s1]);
        float2 n2 = __ldg(&nsd[s2]);
        float2 n3 = __ldg(&nsd[s3]);
        uint2 q0 = *(const uint2*)&h_in[(size_t)s0 * HIDDEN + lane * 4];
        uint2 q1 = *(const uint2*)&h_in[(size_t)s1 * HIDDEN + lane * 4];
        uint2 q2 = *(const uint2*)&h_in[(size_t)s2 * HIDDEN + lane * 4];
        uint2 q3 = *(const uint2*)&h_in[(size_t)s3 * HIDDEN + lane * 4];
        float c0 = tanhf(dtb + n0.x) * dt * n0.y;
        float c1 = tanhf(dtb + n1.x) * dt * n1.y;
        float c2 = tanhf(dtb + n2.x) * dt * n2.y;
        float c3 = tanhf(dtb + n3.x) * dt * n3.y;
        float4 h0 = h4_to_f4(q0), h1 = h4_to_f4(q1);
        float4 h2 = h4_to_f4(q2), h3 = h4_to_f4(q3);
        acc.x = fmaf(c0, h0.x, fmaf(c1, h1.x, fmaf(c2, h2.x, fmaf(c3, h3.x, acc.x))));
        acc.y = fmaf(c0, h0.y, fmaf(c1, h1.y, fmaf(c2, h2.y, fmaf(c3, h3.y, acc.y))));
        acc.z = fmaf(c0, h0.z, fmaf(c1, h1.z, fmaf(c2, h2.z, fmaf(c3, h3.z, acc.z))));
        acc.w = fmaf(c0, h0.w, fmaf(c1, h1.w, fmaf(c2, h2.w, fmaf(c3, h3.w, acc.w))));
    }
    for (; p < re; ++p) {
        int s = __ldg(&g_psrc[p]);
        float2 nn = __ldg(&nsd[s]);
        float ev = tanhf(dtb + nn.x) * dt * nn.y;
        float4 hv = h4_to_f4(*(const uint2*)&h_in[(size_t)s * HIDDEN + lane * 4]);
        acc.x = fmaf(ev, hv.x, acc.x);
        acc.y = fmaf(ev, hv.y, acc.y);
        acc.z = fmaf(ev, hv.z, acc.z);
        acc.w = fmaf(ev, hv.w, acc.w);
    }
    // residual from fp16 raw
    float4 rv = h4_to_f4(*(const uint2*)&g_h0h[(size_t)warp * HIDDEN + lane * 4]);
    float4 o;
    o.x = fmaf(EPS_F, rv.x, acc.x);
    o.y = fmaf(EPS_F, rv.y, acc.y);
    o.z = fmaf(EPS_F, rv.z, acc.z);
    o.w = fmaf(EPS_F, rv.w, acc.w);

    if (LAYER == 0) {
        uint2 st;
        __half2 p01 = __floats2half2_rn(o.x, o.y);
        __half2 p23 = __floats2half2_rn(o.z, o.w);
        st.x = *reinterpret_cast<uint32_t*>(&p01);
        st.y = *reinterpret_cast<uint32_t*>(&p23);
        *(uint2*)&g_hAh[(size_t)warp * HIDDEN + lane * 4] = st;
        // fused next-layer gate scalars
        float4 wd = *(const float4*)&gate_w_next[lane * 4];
        float4 ws = *(const float4*)&gate_w_next[HIDDEN + lane * 4];
        float a0 = o.x * wd.x + o.y * wd.y + o.z * wd.z + o.w * wd.w;
        float a1 = o.x * ws.x + o.y * ws.y + o.z * ws.z + o.w * ws.w;
#pragma unroll
        for (int off = 16; off; off >>= 1) {
            a0 += __shfl_xor_sync(0xffffffffu, a0, off);
            a1 += __shfl_xor_sync(0xffffffffu, a1, off);
        }
        if (lane == 0) {
            g_sdst1[warp] = a0;
            g_nsd1[warp] = make_float2(a1, dt);
        }
    } else {
        *(float4*)&g_hB[(size_t)warp * HIDDEN + lane * 4] = o;
    }
}

// ---------------- final: out = log_softmax(h @ t2_w^T + t2_b) ---------------
__global__ void __launch_bounds__(128)
out_kernel(const float* __restrict__ W2, const float* __restrict__ b2,
           float* __restrict__ out) {
    __shared__ float wt[HIDDEN * OUT_DIM];   // 32KB
    __shared__ float b2s[OUT_DIM];
    __shared__ float hrow[4][4][HIDDEN];     // 8KB
    for (int idx = threadIdx.x; idx < OUT_DIM * HIDDEN; idx += blockDim.x) {
        int j = idx >> 7;
        int k = idx & 127;
        wt[k * OUT_DIM + j] = W2[idx];
    }
    if (threadIdx.x < OUT_DIM) b2s[threadIdx.x] = b2[threadIdx.x];
    __syncthreads();

    const int lane = threadIdx.x & 31;
    const int wlocal = threadIdx.x >> 5;
    const int nwarps = (gridDim.x * blockDim.x) >> 5;

    for (int n0 = (((blockIdx.x * blockDim.x + threadIdx.x) >> 5) << 2);
         n0 < N_NODES; n0 += nwarps * 4) {
#pragma unroll
        for (int i = 0; i < 4; i++) {
            int n = min(n0 + i, N_NODES - 1);
            *(float4*)&hrow[wlocal][i][lane * 4] =
                *(const float4*)&g_hB[(size_t)n * HIDDEN + lane * 4];
        }
        __syncwarp();

        float acc0[4], acc1[4];
#pragma unroll
        for (int i = 0; i < 4; i++) { acc0[i] = b2s[lane]; acc1[i] = b2s[lane + 32]; }
#pragma unroll 4
        for (int k = 0; k < HIDDEN; k++) {
            float w0 = wt[k * OUT_DIM + lane];
            float w1 = wt[k * OUT_DIM + lane + 32];
#pragma unroll
            for (int i = 0; i < 4; i++) {
                float hk = hrow[wlocal][i][k];
                acc0[i] = fmaf(hk, w0, acc0[i]);
                acc1[i] = fmaf(hk, w1, acc1[i]);
            }
        }
#pragma unroll
        for (int i = 0; i < 4; i++) {
            int n = n0 + i;
            if (n >= N_NODES) break;
            float m = fmaxf(acc0[i], acc1[i]);
#pragma unroll
            for (int off = 16; off; off >>= 1)
                m = fmaxf(m, __shfl_xor_sync(0xffffffffu, m, off));
            float s = expf(acc0[i] - m) + expf(acc1[i] - m);
#pragma unroll
            for (int off = 16; off; off >>= 1)
                s += __shfl_xor_sync(0xffffffffu, s, off);
            float lse = m + logf(s);
            out[(size_t)n * OUT_DIM + lane]      = acc0[i] - lse;
            out[(size_t)n * OUT_DIM + lane + 32] = acc1[i] - lse;
        }
        __syncwarp();
    }
}

// ---------------- launch ----------------------------------------------------
extern "C" void kernel_launch(void* const* d_in, const int* in_sizes, int n_in,
                              void* d_out, int out_size) {
    const float* h      = (const float*)d_in[0];
    const int*   src    = (const int*)d_in[1];
    const int*   dst    = (const int*)d_in[2];
    const float* d      = (const float*)d_in[3];
    const float* t1_w   = (const float*)d_in[4];
    const float* t1_b   = (const float*)d_in[5];
    const float* gate_w = (const float*)d_in[6];
    const float* gate_b = (const float*)d_in[7];
    const float* t2_w   = (const float*)d_in[8];
    const float* t2_b   = (const float*)d_in[9];
    float* out = (float*)d_out;

    wconv_kernel<<<(HIDDEN * IN_DIM + 255) / 256, 256>>>(t1_w);
    gemm1_mma_kernel<<<(N_NODES + 127) / 128, 256>>>(h, t1_b, gate_w);

    hist_kernel<<<(N_EDGES + 255) / 256, 256>>>(dst);
    scan_blocks_kernel<<<SCAN_NB, 1024>>>();
    scan_sums_kernel<<<1, 64>>>();
    add_offsets_kernel<<<(N_NODES + 255) / 256, 256>>>(d);
    scatter_kernel<<<(N_EDGES + 255) / 256, 256>>>(src, dst);

    const int node_warp_blocks = (N_NODES * 32 + 255) / 256;  // 6250

    // layer 0: g_h0h -> g_hAh (+ fused coefficients + fused layer-1 gates)
    agg_kernel<0><<<node_warp_blocks, 256>>>(d, gate_b, gate_w + 2 * HIDDEN);
    // layer 1: g_hAh -> g_hB (+ fused coefficients)
    agg_kernel<1><<<node_warp_blocks, 256>>>(d, gate_b, nullptr);

    // output head + log_softmax
    out_kernel<<<592, 128>>>(t2_w, t2_b, out);
}

// round 8
// speedup vs baseline: 1.1343x; 1.1343x over previous
#include <cuda_runtime.h>
#include <cuda_bf16.h>
#include <cuda_fp16.h>
#include <math.h>
#include <stdint.h>

#define N_NODES 50000
#define N_EDGES 800000
#define IN_DIM  512
#define HIDDEN  128
#define OUT_DIM 64
#define EPS_F   0.3f
#define SCAN_NB 49           // ceil(50000/1024)

// ---------------- scratch (device globals; no allocation allowed) -----------
__device__ __half g_h0h[N_NODES * HIDDEN];   // raw fp16 (gathers + residual + gate_proj)
__device__ __half g_hAh[N_NODES * HIDDEN];   // layer-0 out fp16
__device__ float  g_hB [N_NODES * HIDDEN];   // layer-1 out fp32 (head input)
__device__ float  g_sdst[N_NODES];
__device__ float  g_ssrc[N_NODES];
__device__ int    g_counts[N_NODES];
__device__ int    g_rowptr[N_NODES + 1];
__device__ int    g_cursor[N_NODES];
__device__ int    g_psrc[N_EDGES];           // src per CSR position
__device__ int    g_pdst[N_EDGES];           // dst per CSR position
__device__ int2   g_pedge[N_EDGES];          // {src, coef bits} per CSR position
__device__ int    g_blocksums[64];
__device__ __nv_bfloat16 g_w_hi[HIDDEN * IN_DIM];
__device__ __nv_bfloat16 g_w_lo[HIDDEN * IN_DIM];

// ---------------- W split-precision conversion ------------------------------
__global__ void wconv_kernel(const float* __restrict__ W) {
    int i = blockIdx.x * blockDim.x + threadIdx.x;
    if (i < HIDDEN * IN_DIM) {
        float v = W[i];
        __nv_bfloat16 h = __float2bfloat16_rn(v);
        g_w_hi[i] = h;
        g_w_lo[i] = __float2bfloat16_rn(v - __bfloat162float(h));
    }
    if (i < N_NODES) g_counts[i] = 0;   // fused zero_counts
}

// ---------------- GEMM1 via split-bf16 tensor cores --------------------------
#define GP 20  // smem row pitch in 32-bit words

__device__ __forceinline__ uint32_t pack2(__nv_bfloat16 a, __nv_bfloat16 b) {
    uint16_t ua = *reinterpret_cast<uint16_t*>(&a);
    uint16_t ub = *reinterpret_cast<uint16_t*>(&b);
    return (uint32_t)ua | ((uint32_t)ub << 16);
}

__device__ __forceinline__ void mma_bf16(float* d, const uint32_t* a,
                                         uint32_t b0, uint32_t b1) {
    asm volatile(
        "mma.sync.aligned.m16n8k16.row.col.f32.bf16.bf16.f32 "
        "{%0,%1,%2,%3},{%4,%5,%6,%7},{%8,%9},{%0,%1,%2,%3};\n"
        : "+f"(d[0]), "+f"(d[1]), "+f"(d[2]), "+f"(d[3])
        : "r"(a[0]), "r"(a[1]), "r"(a[2]), "r"(a[3]), "r"(b0), "r"(b1));
}

__global__ void __launch_bounds__(256)
gemm1_mma_kernel(const float* __restrict__ A, const float* __restrict__ bias) {
    __shared__ uint32_t asH[128 * GP], asL[128 * GP];
    __shared__ uint32_t bsH[128 * GP], bsL[128 * GP];
    const int tid = threadIdx.x;
    const int brow = blockIdx.x * 128;
    const int warp = tid >> 5, lane = tid & 31;
    const int wm = warp >> 1, wn = warp & 1;
    const int ldrow = tid >> 1, half = tid & 1;

    float acc[2][8][4];
#pragma unroll
    for (int mt = 0; mt < 2; mt++)
#pragma unroll
        for (int nt = 0; nt < 8; nt++)
#pragma unroll
            for (int q = 0; q < 4; q++) acc[mt][nt][q] = 0.f;

    const int arow = min(brow + ldrow, N_NODES - 1);
    const float4* __restrict__ ag =
        (const float4*)&A[(size_t)arow * IN_DIM + half * 16];
    const uint4* __restrict__ bgh =
        (const uint4*)&g_w_hi[ldrow * IN_DIM + half * 16];
    const uint4* __restrict__ bgl =
        (const uint4*)&g_w_lo[ldrow * IN_DIM + half * 16];

    for (int k0 = 0; k0 < IN_DIM; k0 += 32) {
#pragma unroll
        for (int q = 0; q < 4; q++) {
            float4 v = ag[(k0 >> 2) + q];
            __nv_bfloat16 hx = __float2bfloat16_rn(v.x);
            __nv_bfloat16 hy = __float2bfloat16_rn(v.y);
            __nv_bfloat16 hz = __float2bfloat16_rn(v.z);
            __nv_bfloat16 hw = __float2bfloat16_rn(v.w);
            __nv_bfloat16 lx = __float2bfloat16_rn(v.x - __bfloat162float(hx));
            __nv_bfloat16 ly = __float2bfloat16_rn(v.y - __bfloat162float(hy));
            __nv_bfloat16 lz = __float2bfloat16_rn(v.z - __bfloat162float(hz));
            __nv_bfloat16 lw = __float2bfloat16_rn(v.w - __bfloat162float(hw));
            int w = half * 8 + q * 2;
            *(uint2*)&asH[ldrow * GP + w] = make_uint2(pack2(hx, hy), pack2(hz, hw));
            *(uint2*)&asL[ldrow * GP + w] = make_uint2(pack2(lx, ly), pack2(lz, lw));
        }
#pragma unroll
        for (int q = 0; q < 2; q++) {
            uint4 bh = bgh[(k0 >> 3) + q];
            uint4 bl = bgl[(k0 >> 3) + q];
            *(uint4*)&bsH[ldrow * GP + half * 8 + q * 4] = bh;
            *(uint4*)&bsL[ldrow * GP + half * 8 + q * 4] = bl;
        }
        __syncthreads();
#pragma unroll
        for (int kk = 0; kk < 2; kk++) {
            const int kw = kk * 8 + (lane & 3);
            uint32_t aH[2][4], aL[2][4];
#pragma unroll
            for (int mt = 0; mt < 2; mt++) {
                int r = wm * 32 + mt * 16 + (lane >> 2);
                aH[mt][0] = asH[r * GP + kw];
                aH[mt][1] = asH[(r + 8) * GP + kw];
                aH[mt][2] = asH[r * GP + kw + 4];
                aH[mt][3] = asH[(r + 8) * GP + kw + 4];
                aL[mt][0] = asL[r * GP + kw];
                aL[mt][1] = asL[(r + 8) * GP + kw];
                aL[mt][2] = asL[r * GP + kw + 4];
                aL[mt][3] = asL[(r + 8) * GP + kw + 4];
            }
#pragma unroll
            for (int nt = 0; nt < 8; nt++) {
                int n = wn * 64 + nt * 8 + (lane >> 2);
                uint32_t bH0 = bsH[n * GP + kw], bH1 = bsH[n * GP + kw + 4];
                uint32_t bL0 = bsL[n * GP + kw], bL1 = bsL[n * GP + kw + 4];
#pragma unroll
                for (int mt = 0; mt < 2; mt++) {
                    mma_bf16(acc[mt][nt], aH[mt], bH0, bH1);
                    mma_bf16(acc[mt][nt], aL[mt], bH0, bH1);
                    mma_bf16(acc[mt][nt], aH[mt], bL0, bL1);
                }
            }
        }
        __syncthreads();
    }
    // epilogue: bias + relu -> fp16 store only
#pragma unroll
    for (int mt = 0; mt < 2; mt++) {
        int r0 = brow + wm * 32 + mt * 16 + (lane >> 2);
#pragma unroll
        for (int nt = 0; nt < 8; nt++) {
            int c = wn * 64 + nt * 8 + (lane & 3) * 2;
            float b0 = __ldg(&bias[c]), b1 = __ldg(&bias[c + 1]);
            if (r0 < N_NODES) {
                float v0 = fmaxf(acc[mt][nt][0] + b0, 0.f);
                float v1 = fmaxf(acc[mt][nt][1] + b1, 0.f);
                *(__half2*)&g_h0h[(size_t)r0 * HIDDEN + c] = __floats2half2_rn(v0, v1);
            }
            if (r0 + 8 < N_NODES) {
                float v0 = fmaxf(acc[mt][nt][2] + b0, 0.f);
                float v1 = fmaxf(acc[mt][nt][3] + b1, 0.f);
                *(__half2*)&g_h0h[(size_t)(r0 + 8) * HIDDEN + c] = __floats2half2_rn(v0, v1);
            }
        }
    }
}

// ---------------- CSR build -------------------------------------------------
__global__ void hist_kernel(const int* __restrict__ dst) {
    int i = blockIdx.x * blockDim.x + threadIdx.x;
    if (i < N_EDGES) atomicAdd(&g_counts[dst[i]], 1);
}
__global__ void scan_blocks_kernel() {
    __shared__ int wsum[32];
    const int t = threadIdx.x, lane = t & 31, wid = t >> 5;
    const int i = blockIdx.x * 1024 + t;
    int v = (i < N_NODES) ? g_counts[i] : 0;
    int x = v;
#pragma unroll
    for (int off = 1; off < 32; off <<= 1) {
        int y = __shfl_up_sync(0xffffffffu, x, off);
        if (lane >= off) x += y;
    }
    if (lane == 31) wsum[wid] = x;
    __syncthreads();
    if (wid == 0) {
        int s = wsum[lane];
#pragma unroll
        for (int off = 1; off < 32; off <<= 1) {
            int y = __shfl_up_sync(0xffffffffu, s, off);
            if (lane >= off) s += y;
        }
        wsum[lane] = s;
    }
    __syncthreads();
    int incl = x + (wid > 0 ? wsum[wid - 1] : 0);
    if (i < N_NODES) g_rowptr[i] = incl - v;
    if (t == 1023) g_blocksums[blockIdx.x] = incl;
}
__global__ void scan_sums_kernel() {
    __shared__ int sm[64];
    int t = threadIdx.x;
    int v = (t < SCAN_NB) ? g_blocksums[t] : 0;
    sm[t] = v;
    __syncthreads();
    for (int off = 1; off < 64; off <<= 1) {
        int x = (t >= off) ? sm[t - off] : 0;
        __syncthreads();
        sm[t] += x;
        __syncthreads();
    }
    if (t < SCAN_NB) g_blocksums[t] = sm[t] - v;
}
__global__ void add_offsets_kernel() {
    int i = blockIdx.x * blockDim.x + threadIdx.x;
    if (i < N_NODES) {
        int r = g_rowptr[i] + g_blocksums[i >> 10];
        g_rowptr[i] = r;
        g_cursor[i] = r;
    }
    if (i == 0) g_rowptr[N_NODES] = N_EDGES;
}
__global__ void scatter_kernel(const int* __restrict__ src,
                               const int* __restrict__ dst) {
    int i = blockIdx.x * blockDim.x + threadIdx.x;
    if (i < N_EDGES) {
        int t = dst[i];
        int pos = atomicAdd(&g_cursor[t], 1);
        g_psrc[pos] = src[i];
        g_pdst[pos] = t;
    }
}

// ---------------- gate scalar projections (layer 0, fp16 input) --------------
__global__ void gate_proj_kernel(const float* __restrict__ gate_w) {
    int warp = (blockIdx.x * blockDim.x + threadIdx.x) >> 5;
    int lane = threadIdx.x & 31;
    if (warp >= N_NODES) return;
    const float4 wd = *(const float4*)&gate_w[lane * 4];
    const float4 ws = *(const float4*)&gate_w[HIDDEN + lane * 4];
    uint2 q = *(const uint2*)&g_h0h[(size_t)warp * HIDDEN + lane * 4];
    __half2 qa = *reinterpret_cast<__half2*>(&q.x);
    __half2 qb = *reinterpret_cast<__half2*>(&q.y);
    float2 fa = __half22float2(qa), fb = __half22float2(qb);
    float a0 = fa.x * wd.x + fa.y * wd.y + fb.x * wd.z + fb.y * wd.w;
    float a1 = fa.x * ws.x + fa.y * ws.y + fb.x * ws.z + fb.y * ws.w;
#pragma unroll
    for (int off = 16; off; off >>= 1) {
        a0 += __shfl_xor_sync(0xffffffffu, a0, off);
        a1 += __shfl_xor_sync(0xffffffffu, a1, off);
    }
    if (lane == 0) { g_sdst[warp] = a0; g_ssrc[warp] = a1; }
}

// ---------------- per-position edge coefficients (coalesced) ----------------
__global__ void edge_coef_kernel(const float* __restrict__ d,
                                 const float* __restrict__ gate_b, int layer) {
    int p = blockIdx.x * blockDim.x + threadIdx.x;
    if (p >= N_EDGES) return;
    int s = g_psrc[p], t = g_pdst[p];
    float g = tanhf(g_sdst[t] + g_ssrc[s] + gate_b[layer]);
    g_pedge[p] = make_int2(s, __float_as_int(g * d[t] * d[s]));
}

// ---------------- aggregation (fp16 gathers, fp32 accumulate) ---------------
__device__ __forceinline__ float4 h4_to_f4(uint2 q) {
    __half2 a = *reinterpret_cast<__half2*>(&q.x);
    __half2 b = *reinterpret_cast<__half2*>(&q.y);
    float2 fa = __half22float2(a), fb = __half22float2(b);
    return make_float4(fa.x, fa.y, fb.x, fb.y);
}

// LAYER 0: gather g_h0h -> g_hAh fp16, + fused layer-1 gate scalars.
// LAYER 1: gather g_hAh -> g_hB fp32.
template <int LAYER>
__global__ void agg_kernel(const float* __restrict__ gate_w_next) {
    int warp = (blockIdx.x * blockDim.x + threadIdx.x) >> 5;
    int lane = threadIdx.x & 31;
    if (warp >= N_NODES) return;
    const __half* __restrict__ h_in = (LAYER == 0) ? g_h0h : g_hAh;
    int rs = g_rowptr[warp], re = g_rowptr[warp + 1];
    float4 acc = make_float4(0.f, 0.f, 0.f, 0.f);
    int p = rs;
    for (; p + 3 < re; p += 4) {
        int2 e0 = __ldg(&g_pedge[p]);
        int2 e1 = __ldg(&g_pedge[p + 1]);
        int2 e2 = __ldg(&g_pedge[p + 2]);
        int2 e3 = __ldg(&g_pedge[p + 3]);
        uint2 q0 = *(const uint2*)&h_in[(size_t)e0.x * HIDDEN + lane * 4];
        uint2 q1 = *(const uint2*)&h_in[(size_t)e1.x * HIDDEN + lane * 4];
        uint2 q2 = *(const uint2*)&h_in[(size_t)e2.x * HIDDEN + lane * 4];
        uint2 q3 = *(const uint2*)&h_in[(size_t)e3.x * HIDDEN + lane * 4];
        float4 h0 = h4_to_f4(q0), h1 = h4_to_f4(q1);
        float4 h2 = h4_to_f4(q2), h3 = h4_to_f4(q3);
        float c0 = __int_as_float(e0.y), c1 = __int_as_float(e1.y);
        float c2 = __int_as_float(e2.y), c3 = __int_as_float(e3.y);
        acc.x = fmaf(c0, h0.x, fmaf(c1, h1.x, fmaf(c2, h2.x, fmaf(c3, h3.x, acc.x))));
        acc.y = fmaf(c0, h0.y, fmaf(c1, h1.y, fmaf(c2, h2.y, fmaf(c3, h3.y, acc.y))));
        acc.z = fmaf(c0, h0.z, fmaf(c1, h1.z, fmaf(c2, h2.z, fmaf(c3, h3.z, acc.z))));
        acc.w = fmaf(c0, h0.w, fmaf(c1, h1.w, fmaf(c2, h2.w, fmaf(c3, h3.w, acc.w))));
    }
    for (; p < re; ++p) {
        int2 e = __ldg(&g_pedge[p]);
        float ev = __int_as_float(e.y);
        float4 hv = h4_to_f4(*(const uint2*)&h_in[(size_t)e.x * HIDDEN + lane * 4]);
        acc.x = fmaf(ev, hv.x, acc.x);
        acc.y = fmaf(ev, hv.y, acc.y);
        acc.z = fmaf(ev, hv.z, acc.z);
        acc.w = fmaf(ev, hv.w, acc.w);
    }
    // residual from fp16 raw
    float4 rv = h4_to_f4(*(const uint2*)&g_h0h[(size_t)warp * HIDDEN + lane * 4]);
    float4 o;
    o.x = fmaf(EPS_F, rv.x, acc.x);
    o.y = fmaf(EPS_F, rv.y, acc.y);
    o.z = fmaf(EPS_F, rv.z, acc.z);
    o.w = fmaf(EPS_F, rv.w, acc.w);

    if (LAYER == 0) {
        uint2 st;
        __half2 p01 = __floats2half2_rn(o.x, o.y);
        __half2 p23 = __floats2half2_rn(o.z, o.w);
        st.x = *reinterpret_cast<uint32_t*>(&p01);
        st.y = *reinterpret_cast<uint32_t*>(&p23);
        *(uint2*)&g_hAh[(size_t)warp * HIDDEN + lane * 4] = st;
        // fused next-layer gate scalars (fp32 from registers)
        float4 wd = *(const float4*)&gate_w_next[lane * 4];
        float4 ws = *(const float4*)&gate_w_next[HIDDEN + lane * 4];
        float a0 = o.x * wd.x + o.y * wd.y + o.z * wd.z + o.w * wd.w;
        float a1 = o.x * ws.x + o.y * ws.y + o.z * ws.z + o.w * ws.w;
#pragma unroll
        for (int off = 16; off; off >>= 1) {
            a0 += __shfl_xor_sync(0xffffffffu, a0, off);
            a1 += __shfl_xor_sync(0xffffffffu, a1, off);
        }
        if (lane == 0) { g_sdst[warp] = a0; g_ssrc[warp] = a1; }
    } else {
        *(float4*)&g_hB[(size_t)warp * HIDDEN + lane * 4] = o;
    }
}

// ---------------- final: out = log_softmax(h @ t2_w^T + t2_b) ---------------
__global__ void __launch_bounds__(128)
out_kernel(const float* __restrict__ W2, const float* __restrict__ b2,
           float* __restrict__ out) {
    __shared__ float wt[HIDDEN * OUT_DIM];   // 32KB
    __shared__ float b2s[OUT_DIM];
    __shared__ float hrow[4][4][HIDDEN];     // 8KB
    for (int idx = threadIdx.x; idx < OUT_DIM * HIDDEN; idx += blockDim.x) {
        int j = idx >> 7;
        int k = idx & 127;
        wt[k * OUT_DIM + j] = W2[idx];
    }
    if (threadIdx.x < OUT_DIM) b2s[threadIdx.x] = b2[threadIdx.x];
    __syncthreads();

    const int lane = threadIdx.x & 31;
    const int wlocal = threadIdx.x >> 5;
    const int nwarps = (gridDim.x * blockDim.x) >> 5;

    for (int n0 = (((blockIdx.x * blockDim.x + threadIdx.x) >> 5) << 2);
         n0 < N_NODES; n0 += nwarps * 4) {
#pragma unroll
        for (int i = 0; i < 4; i++) {
            int n = min(n0 + i, N_NODES - 1);
            *(float4*)&hrow[wlocal][i][lane * 4] =
                *(const float4*)&g_hB[(size_t)n * HIDDEN + lane * 4];
        }
        __syncwarp();

        float acc0[4], acc1[4];
#pragma unroll
        for (int i = 0; i < 4; i++) { acc0[i] = b2s[lane]; acc1[i] = b2s[lane + 32]; }
#pragma unroll 4
        for (int k = 0; k < HIDDEN; k++) {
            float w0 = wt[k * OUT_DIM + lane];
            float w1 = wt[k * OUT_DIM + lane + 32];
#pragma unroll
            for (int i = 0; i < 4; i++) {
                float hk = hrow[wlocal][i][k];
                acc0[i] = fmaf(hk, w0, acc0[i]);
                acc1[i] = fmaf(hk, w1, acc1[i]);
            }
        }
#pragma unroll
        for (int i = 0; i < 4; i++) {
            int n = n0 + i;
            if (n >= N_NODES) break;
            float m = fmaxf(acc0[i], acc1[i]);
#pragma unroll
            for (int off = 16; off; off >>= 1)
                m = fmaxf(m, __shfl_xor_sync(0xffffffffu, m, off));
            float s = expf(acc0[i] - m) + expf(acc1[i] - m);
#pragma unroll
            for (int off = 16; off; off >>= 1)
                s += __shfl_xor_sync(0xffffffffu, s, off);
            float lse = m + logf(s);
            out[(size_t)n * OUT_DIM + lane]      = acc0[i] - lse;
            out[(size_t)n * OUT_DIM + lane + 32] = acc1[i] - lse;
        }
        __syncwarp();
    }
}

// ---------------- launch ----------------------------------------------------
extern "C" void kernel_launch(void* const* d_in, const int* in_sizes, int n_in,
                              void* d_out, int out_size) {
    const float* h      = (const float*)d_in[0];
    const int*   src    = (const int*)d_in[1];
    const int*   dst    = (const int*)d_in[2];
    const float* d      = (const float*)d_in[3];
    const float* t1_w   = (const float*)d_in[4];
    const float* t1_b   = (const float*)d_in[5];
    const float* gate_w = (const float*)d_in[6];
    const float* gate_b = (const float*)d_in[7];
    const float* t2_w   = (const float*)d_in[8];
    const float* t2_b   = (const float*)d_in[9];
    float* out = (float*)d_out;

    wconv_kernel<<<(HIDDEN * IN_DIM + 255) / 256, 256>>>(t1_w);
    gemm1_mma_kernel<<<(N_NODES + 127) / 128, 256>>>(h, t1_b);

    hist_kernel<<<(N_EDGES + 255) / 256, 256>>>(dst);
    scan_blocks_kernel<<<SCAN_NB, 1024>>>();
    scan_sums_kernel<<<1, 64>>>();
    add_offsets_kernel<<<(N_NODES + 255) / 256, 256>>>();
    scatter_kernel<<<(N_EDGES + 255) / 256, 256>>>(src, dst);

    const int node_warp_blocks = (N_NODES * 32 + 255) / 256;  // 6250
    const int edge_blocks = (N_EDGES + 255) / 256;

    // layer 0: g_h0h -> g_hAh (+ fused layer-1 gate scalars)
    gate_proj_kernel<<<node_warp_blocks, 256>>>(gate_w);
    edge_coef_kernel<<<edge_blocks, 256>>>(d, gate_b, 0);
    agg_kernel<0><<<node_warp_blocks, 256>>>(gate_w + 2 * HIDDEN);

    // layer 1: g_hAh -> g_hB
    edge_coef_kernel<<<edge_blocks, 256>>>(d, gate_b, 1);
    agg_kernel<1><<<node_warp_blocks, 256>>>(nullptr);

    // output head + log_softmax (grid-stride, wt loaded once per block)
    out_kernel<<<592, 128>>>(t2_w, t2_b, out);
}

// round 9
// speedup vs baseline: 1.2326x; 1.0867x over previous
#include <cuda_runtime.h>
#include <cuda_bf16.h>
#include <cuda_fp16.h>
#include <math.h>
#include <stdint.h>

#define N_NODES 50000
#define N_EDGES 800000
#define IN_DIM  512
#define HIDDEN  128
#define OUT_DIM 64
#define EPS_F   0.3f
#define SCAN_NB 49           // ceil(50000/1024)

// ---------------- scratch (device globals; no allocation allowed) -----------
__device__ __half g_h0h[N_NODES * HIDDEN];   // raw fp16 (gathers + residual + gate_proj)
__device__ __half g_hAh[N_NODES * HIDDEN];   // layer-0 out fp16
__device__ float  g_hB [N_NODES * HIDDEN];   // layer-1 out fp32 (head input)
__device__ float  g_sdst[N_NODES];
__device__ float  g_ssrc[N_NODES];
__device__ int    g_counts[N_NODES];
__device__ int    g_rowptr[N_NODES + 1];
__device__ int    g_cursor[N_NODES];
__device__ int    g_psrc[N_EDGES];           // src per CSR position
__device__ int    g_pdst[N_EDGES];           // dst per CSR position
__device__ int2   g_pedge[N_EDGES];          // {src, coef bits} per CSR position
__device__ int    g_blocksums[64];
__device__ __nv_bfloat16 g_w_hi[HIDDEN * IN_DIM];
__device__ __nv_bfloat16 g_w_lo[HIDDEN * IN_DIM];

// ---------------- W split-precision conversion (branch A) -------------------
__global__ void wconv_kernel(const float* __restrict__ W) {
    int i = blockIdx.x * blockDim.x + threadIdx.x;
    if (i < HIDDEN * IN_DIM) {
        float v = W[i];
        __nv_bfloat16 h = __float2bfloat16_rn(v);
        g_w_hi[i] = h;
        g_w_lo[i] = __float2bfloat16_rn(v - __bfloat162float(h));
    }
}

// ---------------- GEMM1 via split-bf16 tensor cores --------------------------
#define GP 20  // smem row pitch in 32-bit words

__device__ __forceinline__ uint32_t pack2(__nv_bfloat16 a, __nv_bfloat16 b) {
    uint16_t ua = *reinterpret_cast<uint16_t*>(&a);
    uint16_t ub = *reinterpret_cast<uint16_t*>(&b);
    return (uint32_t)ua | ((uint32_t)ub << 16);
}

__device__ __forceinline__ void mma_bf16(float* d, const uint32_t* a,
                                         uint32_t b0, uint32_t b1) {
    asm volatile(
        "mma.sync.aligned.m16n8k16.row.col.f32.bf16.bf16.f32 "
        "{%0,%1,%2,%3},{%4,%5,%6,%7},{%8,%9},{%0,%1,%2,%3};\n"
        : "+f"(d[0]), "+f"(d[1]), "+f"(d[2]), "+f"(d[3])
        : "r"(a[0]), "r"(a[1]), "r"(a[2]), "r"(a[3]), "r"(b0), "r"(b1));
}

__global__ void __launch_bounds__(256)
gemm1_mma_kernel(const float* __restrict__ A, const float* __restrict__ bias) {
    __shared__ uint32_t asH[128 * GP], asL[128 * GP];
    __shared__ uint32_t bsH[128 * GP], bsL[128 * GP];
    const int tid = threadIdx.x;
    const int brow = blockIdx.x * 128;
    const int warp = tid >> 5, lane = tid & 31;
    const int wm = warp >> 1, wn = warp & 1;
    const int ldrow = tid >> 1, half = tid & 1;

    float acc[2][8][4];
#pragma unroll
    for (int mt = 0; mt < 2; mt++)
#pragma unroll
        for (int nt = 0; nt < 8; nt++)
#pragma unroll
            for (int q = 0; q < 4; q++) acc[mt][nt][q] = 0.f;

    const int arow = min(brow + ldrow, N_NODES - 1);
    const float4* __restrict__ ag =
        (const float4*)&A[(size_t)arow * IN_DIM + half * 16];
    const uint4* __restrict__ bgh =
        (const uint4*)&g_w_hi[ldrow * IN_DIM + half * 16];
    const uint4* __restrict__ bgl =
        (const uint4*)&g_w_lo[ldrow * IN_DIM + half * 16];

    for (int k0 = 0; k0 < IN_DIM; k0 += 32) {
#pragma unroll
        for (int q = 0; q < 4; q++) {
            float4 v = ag[(k0 >> 2) + q];
            __nv_bfloat16 hx = __float2bfloat16_rn(v.x);
            __nv_bfloat16 hy = __float2bfloat16_rn(v.y);
            __nv_bfloat16 hz = __float2bfloat16_rn(v.z);
            __nv_bfloat16 hw = __float2bfloat16_rn(v.w);
            __nv_bfloat16 lx = __float2bfloat16_rn(v.x - __bfloat162float(hx));
            __nv_bfloat16 ly = __float2bfloat16_rn(v.y - __bfloat162float(hy));
            __nv_bfloat16 lz = __float2bfloat16_rn(v.z - __bfloat162float(hz));
            __nv_bfloat16 lw = __float2bfloat16_rn(v.w - __bfloat162float(hw));
            int w = half * 8 + q * 2;
            *(uint2*)&asH[ldrow * GP + w] = make_uint2(pack2(hx, hy), pack2(hz, hw));
            *(uint2*)&asL[ldrow * GP + w] = make_uint2(pack2(lx, ly), pack2(lz, lw));
        }
#pragma unroll
        for (int q = 0; q < 2; q++) {
            uint4 bh = bgh[(k0 >> 3) + q];
            uint4 bl = bgl[(k0 >> 3) + q];
            *(uint4*)&bsH[ldrow * GP + half * 8 + q * 4] = bh;
            *(uint4*)&bsL[ldrow * GP + half * 8 + q * 4] = bl;
        }
        __syncthreads();
#pragma unroll
        for (int kk = 0; kk < 2; kk++) {
            const int kw = kk * 8 + (lane & 3);
            uint32_t aH[2][4], aL[2][4];
#pragma unroll
            for (int mt = 0; mt < 2; mt++) {
                int r = wm * 32 + mt * 16 + (lane >> 2);
                aH[mt][0] = asH[r * GP + kw];
                aH[mt][1] = asH[(r + 8) * GP + kw];
                aH[mt][2] = asH[r * GP + kw + 4];
                aH[mt][3] = asH[(r + 8) * GP + kw + 4];
                aL[mt][0] = asL[r * GP + kw];
                aL[mt][1] = asL[(r + 8) * GP + kw];
                aL[mt][2] = asL[r * GP + kw + 4];
                aL[mt][3] = asL[(r + 8) * GP + kw + 4];
            }
#pragma unroll
            for (int nt = 0; nt < 8; nt++) {
                int n = wn * 64 + nt * 8 + (lane >> 2);
                uint32_t bH0 = bsH[n * GP + kw], bH1 = bsH[n * GP + kw + 4];
                uint32_t bL0 = bsL[n * GP + kw], bL1 = bsL[n * GP + kw + 4];
#pragma unroll
                for (int mt = 0; mt < 2; mt++) {
                    mma_bf16(acc[mt][nt], aH[mt], bH0, bH1);
                    mma_bf16(acc[mt][nt], aL[mt], bH0, bH1);
                    mma_bf16(acc[mt][nt], aH[mt], bL0, bL1);
                }
            }
        }
        __syncthreads();
    }
    // epilogue: bias + relu -> fp16 store only
#pragma unroll
    for (int mt = 0; mt < 2; mt++) {
        int r0 = brow + wm * 32 + mt * 16 + (lane >> 2);
#pragma unroll
        for (int nt = 0; nt < 8; nt++) {
            int c = wn * 64 + nt * 8 + (lane & 3) * 2;
            float b0 = __ldg(&bias[c]), b1 = __ldg(&bias[c + 1]);
            if (r0 < N_NODES) {
                float v0 = fmaxf(acc[mt][nt][0] + b0, 0.f);
                float v1 = fmaxf(acc[mt][nt][1] + b1, 0.f);
                *(__half2*)&g_h0h[(size_t)r0 * HIDDEN + c] = __floats2half2_rn(v0, v1);
            }
            if (r0 + 8 < N_NODES) {
                float v0 = fmaxf(acc[mt][nt][2] + b0, 0.f);
                float v1 = fmaxf(acc[mt][nt][3] + b1, 0.f);
                *(__half2*)&g_h0h[(size_t)(r0 + 8) * HIDDEN + c] = __floats2half2_rn(v0, v1);
            }
        }
    }
}

// ---------------- CSR build (branch B) ---------------------------------------
__global__ void zero_counts_kernel() {
    int i = blockIdx.x * blockDim.x + threadIdx.x;
    if (i < N_NODES) g_counts[i] = 0;
}
__global__ void hist_kernel(const int* __restrict__ dst) {
    int i = blockIdx.x * blockDim.x + threadIdx.x;
    if (i < N_EDGES) atomicAdd(&g_counts[dst[i]], 1);
}
__global__ void scan_blocks_kernel() {
    __shared__ int wsum[32];
    const int t = threadIdx.x, lane = t & 31, wid = t >> 5;
    const int i = blockIdx.x * 1024 + t;
    int v = (i < N_NODES) ? g_counts[i] : 0;
    int x = v;
#pragma unroll
    for (int off = 1; off < 32; off <<= 1) {
        int y = __shfl_up_sync(0xffffffffu, x, off);
        if (lane >= off) x += y;
    }
    if (lane == 31) wsum[wid] = x;
    __syncthreads();
    if (wid == 0) {
        int s = wsum[lane];
#pragma unroll
        for (int off = 1; off < 32; off <<= 1) {
            int y = __shfl_up_sync(0xffffffffu, s, off);
            if (lane >= off) s += y;
        }
        wsum[lane] = s;
    }
    __syncthreads();
    int incl = x + (wid > 0 ? wsum[wid - 1] : 0);
    if (i < N_NODES) g_rowptr[i] = incl - v;
    if (t == 1023) g_blocksums[blockIdx.x] = incl;
}
__global__ void scan_sums_kernel() {
    __shared__ int sm[64];
    int t = threadIdx.x;
    int v = (t < SCAN_NB) ? g_blocksums[t] : 0;
    sm[t] = v;
    __syncthreads();
    for (int off = 1; off < 64; off <<= 1) {
        int x = (t >= off) ? sm[t - off] : 0;
        __syncthreads();
        sm[t] += x;
        __syncthreads();
    }
    if (t < SCAN_NB) g_blocksums[t] = sm[t] - v;
}
__global__ void add_offsets_kernel() {
    int i = blockIdx.x * blockDim.x + threadIdx.x;
    if (i < N_NODES) {
        int r = g_rowptr[i] + g_blocksums[i >> 10];
        g_rowptr[i] = r;
        g_cursor[i] = r;
    }
    if (i == 0) g_rowptr[N_NODES] = N_EDGES;
}
__global__ void scatter_kernel(const int* __restrict__ src,
                               const int* __restrict__ dst) {
    int i = blockIdx.x * blockDim.x + threadIdx.x;
    if (i < N_EDGES) {
        int t = dst[i];
        int pos = atomicAdd(&g_cursor[t], 1);
        g_psrc[pos] = src[i];
        g_pdst[pos] = t;
    }
}

// ---------------- gate scalar projections (layer 0, fp16 input) --------------
__global__ void gate_proj_kernel(const float* __restrict__ gate_w) {
    int warp = (blockIdx.x * blockDim.x + threadIdx.x) >> 5;
    int lane = threadIdx.x & 31;
    if (warp >= N_NODES) return;
    const float4 wd = *(const float4*)&gate_w[lane * 4];
    const float4 ws = *(const float4*)&gate_w[HIDDEN + lane * 4];
    uint2 q = *(const uint2*)&g_h0h[(size_t)warp * HIDDEN + lane * 4];
    __half2 qa = *reinterpret_cast<__half2*>(&q.x);
    __half2 qb = *reinterpret_cast<__half2*>(&q.y);
    float2 fa = __half22float2(qa), fb = __half22float2(qb);
    float a0 = fa.x * wd.x + fa.y * wd.y + fb.x * wd.z + fb.y * wd.w;
    float a1 = fa.x * ws.x + fa.y * ws.y + fb.x * ws.z + fb.y * ws.w;
#pragma unroll
    for (int off = 16; off; off >>= 1) {
        a0 += __shfl_xor_sync(0xffffffffu, a0, off);
        a1 += __shfl_xor_sync(0xffffffffu, a1, off);
    }
    if (lane == 0) { g_sdst[warp] = a0; g_ssrc[warp] = a1; }
}

// ---------------- per-position edge coefficients (coalesced) ----------------
__global__ void edge_coef_kernel(const float* __restrict__ d,
                                 const float* __restrict__ gate_b, int layer) {
    int p = blockIdx.x * blockDim.x + threadIdx.x;
    if (p >= N_EDGES) return;
    int s = g_psrc[p], t = g_pdst[p];
    float g = tanhf(g_sdst[t] + g_ssrc[s] + gate_b[layer]);
    g_pedge[p] = make_int2(s, __float_as_int(g * d[t] * d[s]));
}

// ---------------- aggregation (fp16 gathers, fp32 accumulate) ---------------
__device__ __forceinline__ float4 h4_to_f4(uint2 q) {
    __half2 a = *reinterpret_cast<__half2*>(&q.x);
    __half2 b = *reinterpret_cast<__half2*>(&q.y);
    float2 fa = __half22float2(a), fb = __half22float2(b);
    return make_float4(fa.x, fa.y, fb.x, fb.y);
}

// LAYER 0: gather g_h0h -> g_hAh fp16, + fused layer-1 gate scalars.
// LAYER 1: gather g_hAh -> g_hB fp32.
template <int LAYER>
__global__ void agg_kernel(const float* __restrict__ gate_w_next) {
    int warp = (blockIdx.x * blockDim.x + threadIdx.x) >> 5;
    int lane = threadIdx.x & 31;
    if (warp >= N_NODES) return;
    const __half* __restrict__ h_in = (LAYER == 0) ? g_h0h : g_hAh;
    int rs = g_rowptr[warp], re = g_rowptr[warp + 1];
    float4 acc = make_float4(0.f, 0.f, 0.f, 0.f);
    int p = rs;
    for (; p + 3 < re; p += 4) {
        int2 e0 = __ldg(&g_pedge[p]);
        int2 e1 = __ldg(&g_pedge[p + 1]);
        int2 e2 = __ldg(&g_pedge[p + 2]);
        int2 e3 = __ldg(&g_pedge[p + 3]);
        uint2 q0 = *(const uint2*)&h_in[(size_t)e0.x * HIDDEN + lane * 4];
        uint2 q1 = *(const uint2*)&h_in[(size_t)e1.x * HIDDEN + lane * 4];
        uint2 q2 = *(const uint2*)&h_in[(size_t)e2.x * HIDDEN + lane * 4];
        uint2 q3 = *(const uint2*)&h_in[(size_t)e3.x * HIDDEN + lane * 4];
        float4 h0 = h4_to_f4(q0), h1 = h4_to_f4(q1);
        float4 h2 = h4_to_f4(q2), h3 = h4_to_f4(q3);
        float c0 = __int_as_float(e0.y), c1 = __int_as_float(e1.y);
        float c2 = __int_as_float(e2.y), c3 = __int_as_float(e3.y);
        acc.x = fmaf(c0, h0.x, fmaf(c1, h1.x, fmaf(c2, h2.x, fmaf(c3, h3.x, acc.x))));
        acc.y = fmaf(c0, h0.y, fmaf(c1, h1.y, fmaf(c2, h2.y, fmaf(c3, h3.y, acc.y))));
        acc.z = fmaf(c0, h0.z, fmaf(c1, h1.z, fmaf(c2, h2.z, fmaf(c3, h3.z, acc.z))));
        acc.w = fmaf(c0, h0.w, fmaf(c1, h1.w, fmaf(c2, h2.w, fmaf(c3, h3.w, acc.w))));
    }
    for (; p < re; ++p) {
        int2 e = __ldg(&g_pedge[p]);
        float ev = __int_as_float(e.y);
        float4 hv = h4_to_f4(*(const uint2*)&h_in[(size_t)e.x * HIDDEN + lane * 4]);
        acc.x = fmaf(ev, hv.x, acc.x);
        acc.y = fmaf(ev, hv.y, acc.y);
        acc.z = fmaf(ev, hv.z, acc.z);
        acc.w = fmaf(ev, hv.w, acc.w);
    }
    // residual from fp16 raw
    float4 rv = h4_to_f4(*(const uint2*)&g_h0h[(size_t)warp * HIDDEN + lane * 4]);
    float4 o;
    o.x = fmaf(EPS_F, rv.x, acc.x);
    o.y = fmaf(EPS_F, rv.y, acc.y);
    o.z = fmaf(EPS_F, rv.z, acc.z);
    o.w = fmaf(EPS_F, rv.w, acc.w);

    if (LAYER == 0) {
        uint2 st;
        __half2 p01 = __floats2half2_rn(o.x, o.y);
        __half2 p23 = __floats2half2_rn(o.z, o.w);
        st.x = *reinterpret_cast<uint32_t*>(&p01);
        st.y = *reinterpret_cast<uint32_t*>(&p23);
        *(uint2*)&g_hAh[(size_t)warp * HIDDEN + lane * 4] = st;
        // fused next-layer gate scalars (fp32 from registers)
        float4 wd = *(const float4*)&gate_w_next[lane * 4];
        float4 ws = *(const float4*)&gate_w_next[HIDDEN + lane * 4];
        float a0 = o.x * wd.x + o.y * wd.y + o.z * wd.z + o.w * wd.w;
        float a1 = o.x * ws.x + o.y * ws.y + o.z * ws.z + o.w * ws.w;
#pragma unroll
        for (int off = 16; off; off >>= 1) {
            a0 += __shfl_xor_sync(0xffffffffu, a0, off);
            a1 += __shfl_xor_sync(0xffffffffu, a1, off);
        }
        if (lane == 0) { g_sdst[warp] = a0; g_ssrc[warp] = a1; }
    } else {
        *(float4*)&g_hB[(size_t)warp * HIDDEN + lane * 4] = o;
    }
}

// ---------------- final: out = log_softmax(h @ t2_w^T + t2_b) ---------------
__global__ void __launch_bounds__(128)
out_kernel(const float* __restrict__ W2, const float* __restrict__ b2,
           float* __restrict__ out) {
    __shared__ float wt[HIDDEN * OUT_DIM];   // 32KB
    __shared__ float b2s[OUT_DIM];
    __shared__ float hrow[4][4][HIDDEN];     // 8KB
    for (int idx = threadIdx.x; idx < OUT_DIM * HIDDEN; idx += blockDim.x) {
        int j = idx >> 7;
        int k = idx & 127;
        wt[k * OUT_DIM + j] = W2[idx];
    }
    if (threadIdx.x < OUT_DIM) b2s[threadIdx.x] = b2[threadIdx.x];
    __syncthreads();

    const int lane = threadIdx.x & 31;
    const int wlocal = threadIdx.x >> 5;
    const int nwarps = (gridDim.x * blockDim.x) >> 5;

    for (int n0 = (((blockIdx.x * blockDim.x + threadIdx.x) >> 5) << 2);
         n0 < N_NODES; n0 += nwarps * 4) {
#pragma unroll
        for (int i = 0; i < 4; i++) {
            int n = min(n0 + i, N_NODES - 1);
            *(float4*)&hrow[wlocal][i][lane * 4] =
                *(const float4*)&g_hB[(size_t)n * HIDDEN + lane * 4];
        }
        __syncwarp();

        float acc0[4], acc1[4];
#pragma unroll
        for (int i = 0; i < 4; i++) { acc0[i] = b2s[lane]; acc1[i] = b2s[lane + 32]; }
#pragma unroll 4
        for (int k = 0; k < HIDDEN; k++) {
            float w0 = wt[k * OUT_DIM + lane];
            float w1 = wt[k * OUT_DIM + lane + 32];
#pragma unroll
            for (int i = 0; i < 4; i++) {
                float hk = hrow[wlocal][i][k];
                acc0[i] = fmaf(hk, w0, acc0[i]);
                acc1[i] = fmaf(hk, w1, acc1[i]);
            }
        }
#pragma unroll
        for (int i = 0; i < 4; i++) {
            int n = n0 + i;
            if (n >= N_NODES) break;
            float m = fmaxf(acc0[i], acc1[i]);
#pragma unroll
            for (int off = 16; off; off >>= 1)
                m = fmaxf(m, __shfl_xor_sync(0xffffffffu, m, off));
            float s = expf(acc0[i] - m) + expf(acc1[i] - m);
#pragma unroll
            for (int off = 16; off; off >>= 1)
                s += __shfl_xor_sync(0xffffffffu, s, off);
            float lse = m + logf(s);
            out[(size_t)n * OUT_DIM + lane]      = acc0[i] - lse;
            out[(size_t)n * OUT_DIM + lane + 32] = acc1[i] - lse;
        }
        __syncwarp();
    }
}

// ---------------- launch ----------------------------------------------------
extern "C" void kernel_launch(void* const* d_in, const int* in_sizes, int n_in,
                              void* d_out, int out_size) {
    const float* h      = (const float*)d_in[0];
    const int*   src    = (const int*)d_in[1];
    const int*   dst    = (const int*)d_in[2];
    const float* d      = (const float*)d_in[3];
    const float* t1_w   = (const float*)d_in[4];
    const float* t1_b   = (const float*)d_in[5];
    const float* gate_w = (const float*)d_in[6];
    const float* gate_b = (const float*)d_in[7];
    const float* t2_w   = (const float*)d_in[8];
    const float* t2_b   = (const float*)d_in[9];
    float* out = (float*)d_out;

    // Fork: branch B (CSR build) runs concurrently with branch A (GEMM chain).
    // Stream/event create+destroy are host-side and capture-time only; the
    // captured graph gains a parallel branch via the event fork/join edges.
    cudaStream_t s2;
    cudaStreamCreate(&s2);
    cudaEvent_t evFork, evJoin;
    cudaEventCreateWithFlags(&evFork, cudaEventDisableTiming);
    cudaEventCreateWithFlags(&evJoin, cudaEventDisableTiming);

    cudaEventRecord(evFork, 0);
    cudaStreamWaitEvent(s2, evFork, 0);

    // --- branch B on s2: CSR build (only reads src/dst) ---
    zero_counts_kernel<<<(N_NODES + 255) / 256, 256, 0, s2>>>();
    hist_kernel<<<(N_EDGES + 255) / 256, 256, 0, s2>>>(dst);
    scan_blocks_kernel<<<SCAN_NB, 1024, 0, s2>>>();
    scan_sums_kernel<<<1, 64, 0, s2>>>();
    add_offsets_kernel<<<(N_NODES + 255) / 256, 256, 0, s2>>>();
    scatter_kernel<<<(N_EDGES + 255) / 256, 256, 0, s2>>>(src, dst);
    cudaEventRecord(evJoin, s2);

    // --- branch A on main stream: transform + gate scalars ---
    wconv_kernel<<<(HIDDEN * IN_DIM + 255) / 256, 256>>>(t1_w);
    gemm1_mma_kernel<<<(N_NODES + 127) / 128, 256>>>(h, t1_b);

    const int node_warp_blocks = (N_NODES * 32 + 255) / 256;  // 6250
    const int edge_blocks = (N_EDGES + 255) / 256;

    gate_proj_kernel<<<node_warp_blocks, 256>>>(gate_w);

    // join: edge_coef needs both branches
    cudaStreamWaitEvent(0, evJoin, 0);

    // layer 0: g_h0h -> g_hAh (+ fused layer-1 gate scalars)
    edge_coef_kernel<<<edge_blocks, 256>>>(d, gate_b, 0);
    agg_kernel<0><<<node_warp_blocks, 256>>>(gate_w + 2 * HIDDEN);

    // layer 1: g_hAh -> g_hB
    edge_coef_kernel<<<edge_blocks, 256>>>(d, gate_b, 1);
    agg_kernel<1><<<node_warp_blocks, 256>>>(nullptr);

    // output head + log_softmax
    out_kernel<<<592, 128>>>(t2_w, t2_b, out);

    cudaStreamDestroy(s2);
    cudaEventDestroy(evFork);
    cudaEventDestroy(evJoin);
}